// round 11
// baseline (speedup 1.0000x reference)
#include <cuda_runtime.h>

#define H 512
#define W 512
#define MASK 511
#define NPLANE (H * W)
#define NTH 512                  // 4 FFTs x 128 threads
#define NBLK 128                 // <= 148 SMs: all co-resident in wave 1

#define FSTRIDE 580              // float2 stride per FFT smem buffer
#define PAD(i) ((i) + ((i) >> 3))

__device__ float2 g_T[NPLANE];   // row spectra, transposed: g_T[kj*512 + r]
__device__ float2 g_Z[NPLANE];   // Z_hat, row-major:        g_Z[ki*512 + kj]

// ---------------------------------------------------- flag-array grid barrier
__device__ volatile unsigned g_flag[2][NBLK];
__device__ volatile unsigned g_rel[2];

__device__ __forceinline__ void bar_arrive(int n, int tid, int blk, const unsigned* fb) {
    __syncthreads();
    __threadfence();
    if (tid == 0) g_flag[n][blk] = fb[n];
}
__device__ __forceinline__ void bar_wait(int n, int tid, int blk,
                                         const unsigned* rb, const unsigned* ft) {
    if (blk == 0) {
        if (tid < NBLK) { while (g_flag[n][tid] < ft[n]) { } }
        __syncthreads();
        __threadfence();
        if (tid == 0) g_rel[n] = rb[n];
    } else {
        if (tid == 0) {
            while (g_rel[n] < rb[n]) { }
            __threadfence();
        }
        __syncthreads();
    }
}

// ------------------------------------------------------------- complex ops
__device__ __forceinline__ float2 cmul(float2 a, float2 b) {
    return make_float2(a.x * b.x - a.y * b.y, a.x * b.y + a.y * b.x);
}
__device__ __forceinline__ float2 cadd(float2 a, float2 b) { return make_float2(a.x + b.x, a.y + b.y); }
__device__ __forceinline__ float2 csub(float2 a, float2 b) { return make_float2(a.x - b.x, a.y - b.y); }

// partial component c at (i,j), computed directly from X, F.
__device__ __forceinline__ float partial_c(const float* __restrict__ X,
                                           const float* __restrict__ F,
                                           int c, int i, int j) {
    int im = (i - 1) & MASK, ip = (i + 1) & MASK;
    int jm = (j - 1) & MASK, jp = (j + 1) & MASK;
    int id = i * W + j;
    const float* xc = X + c * NPLANE;
    float ctr = xc[id];
    float up = xc[im * W + j];
    float dn = xc[ip * W + j];
    float lf = xc[i * W + jm];
    float rt = xc[i * W + jp];
    float u = X[id];
    float v = X[NPLANE + id];
    float dx = (dn - up) * 0.5f;
    float dy = (rt - lf) * 0.5f;
    float lap = (up + dn + lf + rt) - 4.0f * ctr;
    return -(u * dx + v * dy) + 0.1f * lap + F[c * NPLANE + id];
}

// 4-point DFT, natural bin order. SIGN=-1 forward.
template <int SIGN>
__device__ __forceinline__ void dft4(const float2* a, float2* y) {
    float2 s0 = cadd(a[0], a[2]), d0 = csub(a[0], a[2]);
    float2 s1 = cadd(a[1], a[3]), d1 = csub(a[1], a[3]);
    float2 jd = make_float2(-(float)SIGN * d1.y, (float)SIGN * d1.x);  // SIGN*i*d1
    y[0] = cadd(s0, s1);
    y[1] = cadd(d0, jd);
    y[2] = csub(s0, s1);
    y[3] = csub(d0, jd);
}

// 512-pt radix-4 Stockham FFT (4^4 * 2); 128 threads/FFT, 4 elems/thread.
// x[e] = element (t + 128e) in; x[e] = bin (t + 128e) out. 4 syncthreads.
// Twiddles: 1 __sincosf + 3-step power chain per stage (~2 ulp).
template <int SIGN>
__device__ __forceinline__ void fft512_r4(float2* x, float2* sA, float2* sB, int t) {
    float2 y[4];
    // stage 0: s=1, n=512, p=t, q=0
    dft4<SIGN>(x, y);
    {
        float sn, cs;
        __sincosf((float)SIGN * 0.012271846303085130f * (float)t, &sn, &cs);  // 2π t/512
        float2 w1 = make_float2(cs, sn);
        float2 w2 = cmul(w1, w1);
        y[1] = cmul(y[1], w1);
        y[2] = cmul(y[2], w2);
        y[3] = cmul(y[3], cmul(w2, w1));
#pragma unroll
        for (int e = 0; e < 4; ++e) sA[PAD(4 * t + e)] = y[e];
    }
    __syncthreads();
#pragma unroll
    for (int e = 0; e < 4; ++e) x[e] = sA[PAD(t + 128 * e)];
    // stage 1: s=4, n=128, p=t>>2, q=t&3
    dft4<SIGN>(x, y);
    {
        int p = t >> 2, q = t & 3;
        float sn, cs;
        __sincosf((float)SIGN * 0.049087385212340519f * (float)p, &sn, &cs);  // 2π p/128
        float2 w1 = make_float2(cs, sn);
        float2 w2 = cmul(w1, w1);
        y[1] = cmul(y[1], w1);
        y[2] = cmul(y[2], w2);
        y[3] = cmul(y[3], cmul(w2, w1));
        int wb = q + 16 * p;
#pragma unroll
        for (int e = 0; e < 4; ++e) sB[PAD(wb + 4 * e)] = y[e];
    }
    __syncthreads();
#pragma unroll
    for (int e = 0; e < 4; ++e) x[e] = sB[PAD(t + 128 * e)];
    // stage 2: s=16, n=32, p=t>>4, q=t&15
    dft4<SIGN>(x, y);
    {
        int p = t >> 4, q = t & 15;
        float sn, cs;
        __sincosf((float)SIGN * 0.19634954084936207f * (float)p, &sn, &cs);   // 2π p/32
        float2 w1 = make_float2(cs, sn);
        float2 w2 = cmul(w1, w1);
        y[1] = cmul(y[1], w1);
        y[2] = cmul(y[2], w2);
        y[3] = cmul(y[3], cmul(w2, w1));
        int wb = q + 64 * p;
#pragma unroll
        for (int e = 0; e < 4; ++e) sA[PAD(wb + 16 * e)] = y[e];
    }
    __syncthreads();
#pragma unroll
    for (int e = 0; e < 4; ++e) x[e] = sA[PAD(t + 128 * e)];
    // stage 3: s=64, n=8, p=t>>6 (0 or 1), q=t&63
    dft4<SIGN>(x, y);
    {
        int p = t >> 6, q = t & 63;
        float sn, cs;
        __sincosf((float)SIGN * 0.78539816339744831f * (float)p, &sn, &cs);   // 2π p/8
        float2 w1 = make_float2(cs, sn);
        float2 w2 = cmul(w1, w1);
        y[1] = cmul(y[1], w1);
        y[2] = cmul(y[2], w2);
        y[3] = cmul(y[3], cmul(w2, w1));
        int wb = q + 256 * p;
#pragma unroll
        for (int e = 0; e < 4; ++e) sB[PAD(wb + 64 * e)] = y[e];
    }
    __syncthreads();
#pragma unroll
    for (int e = 0; e < 4; ++e) x[e] = sB[PAD(t + 128 * e)];
    // stage 4: radix-2, s=256, p=0 (twiddle-free), register-resident.
    // pairs (x0,x2)=(elem t, t+256) -> bins t, t+256 ; (x1,x3) -> bins t+128, t+384
    y[0] = cadd(x[0], x[2]);
    y[2] = csub(x[0], x[2]);
    y[1] = cadd(x[1], x[3]);
    y[3] = csub(x[1], x[3]);
#pragma unroll
    for (int e = 0; e < 4; ++e) x[e] = y[e];
}

// Multiplier M = T(ki,kj)/N^2 · (−sy + i·sx). Accurate path (round-9 proven).
__device__ __forceinline__ float2 jacobi_M(int ki, int kj) {
    const float invN2 = 1.0f / 262144.0f;
    float sx = __sinf(0.012271846303085130f * (float)ki);   // sin(2π ki/512)
    float sy = __sinf(0.012271846303085130f * (float)kj);
    float sa = sinf(0.0061359231515f * (float)ki);          // sin(π ki/512)
    float sb = sinf(0.0061359231515f * (float)kj);
    float oms = sa * sa + sb * sb;                          // 1 - s (no cancellation)
    float T;
    if (oms <= 0.0f) {
        T = -249.0f * invN2;                                // ki=kj=0
    } else {
        float arg = 500.0f * log1pf(-oms * (2.0f - oms));   // log(s^1000)
        float s1000 = (arg < -87.0f) ? 0.0f : expf(arg);
        T = (s1000 - (1.0f - s1000) / (4.0f * oms)) * invN2;
    }
    return make_float2(-T * sy, T * sx);
}

// ------------------------------------------------------------- fused kernel
__global__ void __launch_bounds__(NTH) k_fused(const float* __restrict__ X,
                                               const float* __restrict__ F,
                                               float* __restrict__ out) {
    __shared__ float2 sm[2 * 4 * FSTRIDE];      // 4 FFTs x 2 buffers
    const int tid = threadIdx.x;
    const int blk = blockIdx.x;
    const int f = tid >> 7;                     // FFT index within block (0..3)
    const int t = tid & 127;                    // thread within FFT
    float2* sA = sm + f * FSTRIDE;
    float2* sB = sm + (4 + f) * FSTRIDE;

    // barrier bookkeeping (monotonic counters; replay-safe)
    unsigned fb[2] = {0, 0}, rb[2] = {0, 0}, ft[2] = {0, 0};
    if (tid == 0) {
        fb[0] = g_flag[0][blk] + 1;  fb[1] = g_flag[1][blk] + 1;
        rb[0] = g_rel[0] + 1;        rb[1] = g_rel[1] + 1;
    }
    if (blk == 0 && tid < NBLK) {
        ft[0] = g_flag[0][tid] + 1;  ft[1] = g_flag[1][tid] + 1;
    }

    // ================= Phase A: B inline + fwd row FFT, transposed store
    {
        int r = blk * 4 + f;
        int rp = (r + 1) & MASK, rm = (r - 1) & MASK;
        float2 x[4];
#pragma unroll
        for (int e = 0; e < 4; ++e) {
            int j = t + 128 * e;
            int jp = (j + 1) & MASK, jm = (j - 1) & MASK;
            float b = ((partial_c(X, F, 0, rp, j) - partial_c(X, F, 0, rm, j))
                     + (partial_c(X, F, 1, r, jp) - partial_c(X, F, 1, r, jm))) * 5.0f;
            x[e] = make_float2(b, 0.0f);
        }
        fft512_r4<-1>(x, sA, sB, t);

        // smem exchange -> coalesced transposed stores to g_T[kj][r]
        __syncthreads();
#pragma unroll
        for (int e = 0; e < 4; ++e) sm[(t + 128 * e) * 5 + f] = x[e];
        __syncthreads();
        int r0 = blk * 4;
#pragma unroll
        for (int k = 0; k < 4; ++k) {
            int g = tid + NTH * k;              // g in [0, 2048)
            int bin = g >> 2, ff = g & 3;
            g_T[bin * W + r0 + ff] = sm[bin * 5 + ff];
        }
    }
    bar_arrive(0, tid, blk, fb);

    // ---- phase-B prologue (index-only): spectral multiplier, overlaps barrier
    int c = blk * 4 + f;                        // kj
    float2 m[4];
#pragma unroll
    for (int e = 0; e < 4; ++e) m[e] = jacobi_M(t + 128 * e, c);
    bar_wait(0, tid, blk, rb, ft);

    // ================= Phase B: col fwd FFT, multiply, col inv FFT
    {
        float2 x[4];
#pragma unroll
        for (int e = 0; e < 4; ++e) x[e] = g_T[c * W + t + 128 * e];   // coalesced
        fft512_r4<-1>(x, sA, sB, t);
#pragma unroll
        for (int e = 0; e < 4; ++e) x[e] = cmul(x[e], m[e]);
        fft512_r4<1>(x, sA, sB, t);
#pragma unroll
        for (int e = 0; e < 4; ++e) g_Z[(t + 128 * e) * W + c] = x[e];  // scattered stores
    }
    bar_arrive(1, tid, blk, fb);

    // ---- phase-C prologue (reads only X,F): partial recompute, overlaps barrier
    int r = blk * 4 + f;
    float p0[4], p1[4];
#pragma unroll
    for (int e = 0; e < 4; ++e) {
        int j = t + 128 * e;
        p0[e] = partial_c(X, F, 0, r, j);
        p1[e] = partial_c(X, F, 1, r, j);
    }
    bar_wait(1, tid, blk, rb, ft);

    // ================= Phase C: inverse row FFT + epilogue
    {
        float2 x[4];
#pragma unroll
        for (int e = 0; e < 4; ++e) x[e] = g_Z[r * W + t + 128 * e];    // coalesced
        fft512_r4<1>(x, sA, sB, t);
#pragma unroll
        for (int e = 0; e < 4; ++e) {
            int id = r * W + t + 128 * e;
            out[id]          = p0[e] - x[e].x;    // gx = Re
            out[NPLANE + id] = p1[e] - x[e].y;    // gy = Im
        }
    }
}

extern "C" void kernel_launch(void* const* d_in, const int* in_sizes, int n_in,
                              void* d_out, int out_size) {
    const float* X = (const float*)d_in[1];
    const float* F = (const float*)d_in[2];
    float* out = (float*)d_out;
    k_fused<<<NBLK, NTH>>>(X, F, out);
}